// round 1
// baseline (speedup 1.0000x reference)
#include <cuda_runtime.h>
#include <math.h>

#define BB   64
#define TT   32
#define HID  3
#define G    64
#define GG   4096
#define NOC  12
#define EPSV 1e-5f
#define FK   37
#define OUTW 28

// ---------------- static device scratch (no allocations allowed) ----------------
__device__ float g_h[BB*HID*GG];
__device__ float g_c[BB*HID*GG];
__device__ float g_z[BB*NOC*GG];
__device__ float g_part[BB*16*4*2];
__device__ float g_stats[BB*4*2];

// ---------------- init: zero h and c ----------------
__global__ void k_init() {
    int i = blockIdx.x * blockDim.x + threadIdx.x;
    if (i < BB*HID*GG) { g_h[i] = 0.f; g_c[i] = 0.f; }
}

// ---------------- per-step conv (4ch -> 12ch, 11x11, pad 5) + LN partial sums ---
// grid: BB*16 blocks (16x16 output tile per block), 128 threads, 2 px / thread
__global__ __launch_bounds__(128) void k_conv(const float* __restrict__ x,
                                              const float* __restrict__ Wg,
                                              const float* __restrict__ bg,
                                              int t)
{
    __shared__ __align__(16) float ts[4*26*28];     // input tile, padded row stride 28
    __shared__ __align__(16) float wsm[4*121*12];   // weights as [ic][ky][kx][oc]
    __shared__ float sred[4][8];

    const int tid  = threadIdx.x;
    const int b    = blockIdx.x >> 4;
    const int tile = blockIdx.x & 15;
    const int ty0  = (tile >> 2) << 4;
    const int tx0  = (tile & 3) << 4;

    // weights: wsm[(ic*121+kk)*12 + oc] = Wg[(oc*4+ic)*121 + kk]
    for (int i = tid; i < 4*121*12; i += 128) {
        int oc = i % 12;
        int k  = i / 12;
        int ic = k / 121;
        int kk = k - ic*121;
        wsm[i] = Wg[(oc*4 + ic)*121 + kk];
    }
    // input tile: channel 0 = x_t, channels 1..3 = h
    const float* xb = x + (size_t)(b*TT + t) * GG;
    for (int i = tid; i < 4*26*26; i += 128) {
        int ic = i / 676;
        int r  = (i - ic*676) / 26;
        int cc = i % 26;
        int gy = ty0 - 5 + r;
        int gx = tx0 - 5 + cc;
        float v = 0.f;
        if (gy >= 0 && gy < G && gx >= 0 && gx < G) {
            v = (ic == 0) ? xb[gy*G + gx]
                          : g_h[(b*HID + ic - 1)*GG + gy*G + gx];
        }
        ts[(ic*26 + r)*28 + cc] = v;
    }
    __syncthreads();

    const int ty  = tid >> 3;           // 0..15
    const int tx2 = (tid & 7) << 1;     // 0,2,..,14 (local output x base)

    float acc0[12], acc1[12];
    #pragma unroll
    for (int oc = 0; oc < 12; oc++) { acc0[oc] = 0.f; acc1[oc] = 0.f; }

    #pragma unroll 1
    for (int ic = 0; ic < 4; ic++) {
        #pragma unroll 1
        for (int ky = 0; ky < 11; ky++) {
            const float* rowp = &ts[(ic*26 + ty + ky)*28 + tx2];
            float win[12];
            #pragma unroll
            for (int w = 0; w < 6; w++) {
                float2 v = ((const float2*)rowp)[w];
                win[2*w] = v.x; win[2*w+1] = v.y;
            }
            const float4* wp4 = (const float4*)&wsm[(ic*121 + ky*11)*12];
            #pragma unroll
            for (int kx = 0; kx < 11; kx++) {
                float4 wa = wp4[kx*3 + 0];
                float4 wb = wp4[kx*3 + 1];
                float4 wc = wp4[kx*3 + 2];
                float wv[12];
                wv[0]=wa.x; wv[1]=wa.y; wv[2]=wa.z;  wv[3]=wa.w;
                wv[4]=wb.x; wv[5]=wb.y; wv[6]=wb.z;  wv[7]=wb.w;
                wv[8]=wc.x; wv[9]=wc.y; wv[10]=wc.z; wv[11]=wc.w;
                float i0 = win[kx];
                float i1 = win[kx+1];
                #pragma unroll
                for (int oc = 0; oc < 12; oc++) {
                    acc0[oc] = fmaf(i0, wv[oc], acc0[oc]);
                    acc1[oc] = fmaf(i1, wv[oc], acc1[oc]);
                }
            }
        }
    }

    // bias, store z, LN partial sums
    const int gy = ty0 + ty;
    const int gx = tx0 + tx2;
    float s[4]  = {0.f,0.f,0.f,0.f};
    float ss[4] = {0.f,0.f,0.f,0.f};
    #pragma unroll
    for (int oc = 0; oc < 12; oc++) {
        float z0 = acc0[oc] + bg[oc];
        float z1 = acc1[oc] + bg[oc];
        int gt = oc / 3;
        s[gt]  += z0 + z1;
        ss[gt] += z0*z0 + z1*z1;
        float2 zz; zz.x = z0; zz.y = z1;
        *(float2*)&g_z[(size_t)(b*12 + oc)*GG + gy*G + gx] = zz;
    }

    // block reduction of 8 values (s[4], ss[4])
    const int lane = tid & 31;
    const int wrp  = tid >> 5;
    #pragma unroll
    for (int g = 0; g < 4; g++) {
        #pragma unroll
        for (int off = 16; off > 0; off >>= 1) {
            s[g]  += __shfl_down_sync(0xFFFFFFFFu, s[g],  off);
            ss[g] += __shfl_down_sync(0xFFFFFFFFu, ss[g], off);
        }
    }
    if (lane == 0) {
        #pragma unroll
        for (int g = 0; g < 4; g++) {
            sred[wrp][g*2 + 0] = s[g];
            sred[wrp][g*2 + 1] = ss[g];
        }
    }
    __syncthreads();
    if (tid < 8) {
        float v = sred[0][tid] + sred[1][tid] + sred[2][tid] + sred[3][tid];
        // tid = g*2 + which
        g_part[((b*16 + tile)*4 + (tid >> 1))*2 + (tid & 1)] = v;
    }
}

// ---------------- finalize LayerNorm stats: one value per (b, gate) -------------
__global__ void k_stats()
{
    int tid = threadIdx.x;
    if (tid >= 256) return;
    int b  = tid >> 2;
    int gt = tid & 3;
    float s = 0.f, ssum = 0.f;
    #pragma unroll
    for (int tl = 0; tl < 16; tl++) {
        s    += g_part[((b*16 + tl)*4 + gt)*2 + 0];
        ssum += g_part[((b*16 + tl)*4 + gt)*2 + 1];
    }
    const float inv = 1.f / 12288.f;
    float mu  = s * inv;
    float var = fmaxf(ssum * inv - mu*mu, 0.f);
    g_stats[(b*4 + gt)*2 + 0] = mu;
    g_stats[(b*4 + gt)*2 + 1] = rsqrtf(var + EPSV);
}

// ---------------- pointwise gate update ----------------
__global__ void k_gates(const float* __restrict__ wci,
                        const float* __restrict__ wcf,
                        const float* __restrict__ wco,
                        const float* __restrict__ lnw,
                        const float* __restrict__ lnb)
{
    int i = blockIdx.x * 256 + threadIdx.x;   // < BB*HID*GG
    int b = i / (HID*GG);
    int r = i - b*HID*GG;                     // hc*GG + p
    const float* st = &g_stats[b*8];
    size_t base = (size_t)b * 12 * GG;
    float zi = g_z[base + 0*GG*3 + r];
    float zf = g_z[base + 1*GG*3 + r];
    float zg = g_z[base + 2*GG*3 + r];
    float zo = g_z[base + 3*GG*3 + r];
    zi = (zi - st[0]) * st[1] * lnw[0*12288 + r] + lnb[0*12288 + r];
    zf = (zf - st[2]) * st[3] * lnw[1*12288 + r] + lnb[1*12288 + r];
    zg = (zg - st[4]) * st[5] * lnw[2*12288 + r] + lnb[2*12288 + r];
    zo = (zo - st[6]) * st[7] * lnw[3*12288 + r] + lnb[3*12288 + r];
    float c  = g_c[i];
    float ig = 1.f / (1.f + expf(-(zi + wci[r]*c)));
    float fg = 1.f / (1.f + expf(-(zf + wcf[r]*c)));
    float cn = fg*c + ig*tanhf(zg);
    float og = 1.f / (1.f + expf(-(zo + wco[r]*cn)));
    g_c[i] = cn;
    g_h[i] = og * tanhf(cn);
}

// ---------------- final 37x37 valid conv: h(64,3,64,64) -> out(64,1,28,28) ------
// grid: BB*7 blocks; each block does 4 output rows of one image.
__global__ __launch_bounds__(128) void k_final(const float* __restrict__ cw,
                                               const float* __restrict__ cb,
                                               float* __restrict__ out)
{
    __shared__ float hs[40*64];
    __shared__ float ws[FK*FK];
    const int b   = blockIdx.x / 7;
    const int seg = blockIdx.x % 7;
    const int oy0 = seg * 4;
    const int tid = threadIdx.x;
    const int ly  = tid / 28;      // 0..3 for tid<112
    const int ox  = tid % 28;

    float acc = 0.f;
    for (int hc = 0; hc < HID; hc++) {
        __syncthreads();
        for (int i = tid; i < 40*64; i += 128) {
            int r = i / 64;
            hs[i] = g_h[(size_t)(b*HID + hc)*GG + (oy0 + r)*G + (i - r*64)];
        }
        for (int i = tid; i < FK*FK; i += 128) ws[i] = cw[hc*FK*FK + i];
        __syncthreads();
        if (tid < 112) {
            #pragma unroll 1
            for (int ky = 0; ky < FK; ky++) {
                const float* hr = &hs[(ly + ky)*64 + ox];
                const float* wr = &ws[ky*FK];
                float a = 0.f;
                #pragma unroll
                for (int kx = 0; kx < FK; kx++) a = fmaf(hr[kx], wr[kx], a);
                acc += a;
            }
        }
    }
    if (tid < 112) {
        int oy = oy0 + ly;
        out[b*OUTW*OUTW + oy*OUTW + ox] = acc + cb[0];
    }
}

// ---------------- launch ----------------
extern "C" void kernel_launch(void* const* d_in, const int* in_sizes, int n_in,
                              void* d_out, int out_size)
{
    const float* x   = (const float*)d_in[0];
    const float* Wg  = (const float*)d_in[1];
    const float* bg  = (const float*)d_in[2];
    const float* wci = (const float*)d_in[3];
    const float* wcf = (const float*)d_in[4];
    const float* wco = (const float*)d_in[5];
    const float* lnw = (const float*)d_in[6];
    const float* lnb = (const float*)d_in[7];
    const float* cw  = (const float*)d_in[8];
    const float* cb  = (const float*)d_in[9];
    float* out = (float*)d_out;

    k_init<<<(BB*HID*GG + 255)/256, 256>>>();
    for (int t = 0; t < TT; t++) {
        k_conv<<<BB*16, 128>>>(x, Wg, bg, t);
        k_stats<<<1, 256>>>();
        k_gates<<<(BB*HID*GG)/256, 256>>>(wci, wcf, wco, lnw, lnb);
    }
    k_final<<<BB*7, 128>>>(cw, cb, out);
}

// round 2
// speedup vs baseline: 1.2483x; 1.2483x over previous
#include <cuda_runtime.h>
#include <math.h>

#define BB   64
#define TT   32
#define HID  3
#define G    64
#define GG   4096
#define NOC  12
#define EPSV 1e-5f
#define FK   37
#define OUTW 28

typedef unsigned long long u64;

// ---------------- packed f32x2 helpers (Blackwell FFMA2 path) ----------------
__device__ __forceinline__ u64 pack2(float x) {
    u64 d; unsigned u = __float_as_uint(x);
    asm("mov.b64 %0, {%1, %1};" : "=l"(d) : "r"(u));
    return d;
}
__device__ __forceinline__ void ffma2(u64 &acc, u64 a, u64 b) {
    asm("fma.rn.f32x2 %0, %1, %2, %0;" : "+l"(acc) : "l"(a), "l"(b));
}
__device__ __forceinline__ void unpack2(u64 d, float &lo, float &hi) {
    unsigned a, b;
    asm("mov.b64 {%0, %1}, %2;" : "=r"(a), "=r"(b) : "l"(d));
    lo = __uint_as_float(a); hi = __uint_as_float(b);
}

// fast sigmoid: 1/(1+2^(-x*log2e)) via ex2.approx + rcp.approx (~1e-6 rel err)
__device__ __forceinline__ float fsig(float x) {
    float t, r;
    asm("mul.f32 %0, %1, 0fBFB8AA3B;" : "=f"(t) : "f"(x));   // -x*log2(e)
    asm("ex2.approx.f32 %0, %0;" : "+f"(t));
    asm("add.f32 %0, %0, 0f3F800000;" : "+f"(t));
    asm("rcp.approx.f32 %0, %1;" : "=f"(r) : "f"(t));
    return r;
}
// tanh(x) = 2*sigmoid(2x) - 1 (accurate to ~1e-6, avoids coarse tanh.approx)
__device__ __forceinline__ float ftanh(float x) {
    return fmaf(2.f, fsig(2.f * x), -1.f);
}

// ---------------- static device scratch (no allocations allowed) ----------------
__device__ float g_h[BB*HID*GG];
__device__ float g_c[BB*HID*GG];
__device__ float g_z[BB*NOC*GG];
__device__ float g_part[BB*16*4*2];

// ---------------- init: zero h and c ----------------
__global__ void k_init() {
    int i = blockIdx.x * blockDim.x + threadIdx.x;
    if (i < BB*HID*GG) { g_h[i] = 0.f; g_c[i] = 0.f; }
}

// ---------------- per-step conv (4ch -> 12ch, 11x11, pad 5) + LN partial sums ---
// grid: BB*16 blocks (16x16 output tile per block), 128 threads, 2 px / thread
// inner loop: FFMA2 over output-channel pairs (weights packed naturally in smem)
__global__ __launch_bounds__(128) void k_conv(const float* __restrict__ x,
                                              const float* __restrict__ Wg,
                                              const float* __restrict__ bg,
                                              int t)
{
    __shared__ __align__(16) float ts[4*26*28];     // input tile, padded row stride 28
    __shared__ __align__(16) float wsm[4*121*12];   // weights as [ic][ky][kx][oc]
    __shared__ float sred[4][8];

    const int tid  = threadIdx.x;
    const int b    = blockIdx.x >> 4;
    const int tile = blockIdx.x & 15;
    const int ty0  = (tile >> 2) << 4;
    const int tx0  = (tile & 3) << 4;

    // weights: wsm[(ic*121+kk)*12 + oc] = Wg[(oc*4+ic)*121 + kk]
    for (int i = tid; i < 4*121*12; i += 128) {
        int oc = i % 12;
        int k  = i / 12;
        int ic = k / 121;
        int kk = k - ic*121;
        wsm[i] = Wg[(oc*4 + ic)*121 + kk];
    }
    // input tile: channel 0 = x_t, channels 1..3 = h
    const float* xb = x + (size_t)(b*TT + t) * GG;
    for (int i = tid; i < 4*26*26; i += 128) {
        int ic = i / 676;
        int r  = (i - ic*676) / 26;
        int cc = i % 26;
        int gy = ty0 - 5 + r;
        int gx = tx0 - 5 + cc;
        float v = 0.f;
        if (gy >= 0 && gy < G && gx >= 0 && gx < G) {
            v = (ic == 0) ? xb[gy*G + gx]
                          : g_h[(b*HID + ic - 1)*GG + gy*G + gx];
        }
        ts[(ic*26 + r)*28 + cc] = v;
    }
    __syncthreads();

    const int ty  = tid >> 3;           // 0..15
    const int tx2 = (tid & 7) << 1;     // 0,2,..,14 (local output x base)

    // packed accumulators: accA = pixel0, accB = pixel1; each j holds oc pair (2j,2j+1)
    u64 accA[6], accB[6];
    #pragma unroll
    for (int j = 0; j < 6; j++) { accA[j] = 0ull; accB[j] = 0ull; }

    #pragma unroll 1
    for (int ic = 0; ic < 4; ic++) {
        #pragma unroll 1
        for (int ky = 0; ky < 11; ky++) {
            const float* rowp = &ts[(ic*26 + ty + ky)*28 + tx2];
            float win[12];
            #pragma unroll
            for (int w = 0; w < 6; w++) {
                float2 v = ((const float2*)rowp)[w];
                win[2*w] = v.x; win[2*w+1] = v.y;
            }
            const ulonglong2* wp = (const ulonglong2*)&wsm[(ic*121 + ky*11)*12];
            #pragma unroll
            for (int kx = 0; kx < 11; kx++) {
                ulonglong2 p0 = wp[kx*3 + 0];
                ulonglong2 p1 = wp[kx*3 + 1];
                ulonglong2 p2 = wp[kx*3 + 2];
                u64 wv[6];
                wv[0]=p0.x; wv[1]=p0.y; wv[2]=p1.x; wv[3]=p1.y; wv[4]=p2.x; wv[5]=p2.y;
                u64 i0 = pack2(win[kx]);
                u64 i1 = pack2(win[kx+1]);
                #pragma unroll
                for (int j = 0; j < 6; j++) {
                    ffma2(accA[j], i0, wv[j]);
                    ffma2(accB[j], i1, wv[j]);
                }
            }
        }
    }

    // unpack, bias, store z, LN partial sums
    float acc0[12], acc1[12];
    #pragma unroll
    for (int j = 0; j < 6; j++) {
        unpack2(accA[j], acc0[2*j], acc0[2*j+1]);
        unpack2(accB[j], acc1[2*j], acc1[2*j+1]);
    }
    const int gy = ty0 + ty;
    const int gx = tx0 + tx2;
    float s[4]  = {0.f,0.f,0.f,0.f};
    float ss[4] = {0.f,0.f,0.f,0.f};
    #pragma unroll
    for (int oc = 0; oc < 12; oc++) {
        float z0 = acc0[oc] + bg[oc];
        float z1 = acc1[oc] + bg[oc];
        int gt = oc / 3;
        s[gt]  += z0 + z1;
        ss[gt] += z0*z0 + z1*z1;
        float2 zz; zz.x = z0; zz.y = z1;
        *(float2*)&g_z[(size_t)(b*12 + oc)*GG + gy*G + gx] = zz;
    }

    // block reduction of 8 values (s[4], ss[4])
    const int lane = tid & 31;
    const int wrp  = tid >> 5;
    #pragma unroll
    for (int g = 0; g < 4; g++) {
        #pragma unroll
        for (int off = 16; off > 0; off >>= 1) {
            s[g]  += __shfl_down_sync(0xFFFFFFFFu, s[g],  off);
            ss[g] += __shfl_down_sync(0xFFFFFFFFu, ss[g], off);
        }
    }
    if (lane == 0) {
        #pragma unroll
        for (int g = 0; g < 4; g++) {
            sred[wrp][g*2 + 0] = s[g];
            sred[wrp][g*2 + 1] = ss[g];
        }
    }
    __syncthreads();
    if (tid < 8) {
        float v = sred[0][tid] + sred[1][tid] + sred[2][tid] + sred[3][tid];
        g_part[((b*16 + tile)*4 + (tid >> 1))*2 + (tid & 1)] = v;
    }
}

// ---------------- pointwise gate update (with fused LN-stats finalize) ----------
__global__ __launch_bounds__(256) void k_gates(const float* __restrict__ wci,
                                               const float* __restrict__ wcf,
                                               const float* __restrict__ wco,
                                               const float* __restrict__ lnw,
                                               const float* __restrict__ lnb)
{
    __shared__ float st[8];
    int i = blockIdx.x * 256 + threadIdx.x;   // < BB*HID*GG; block spans one b
    int b = i / (HID*GG);
    int r = i - b*HID*GG;                     // hc*GG + p

    // finalize LN stats for this batch (redundant per block, but trivial)
    if (threadIdx.x < 4) {
        int gt = threadIdx.x;
        float s = 0.f, ssum = 0.f;
        #pragma unroll
        for (int tl = 0; tl < 16; tl++) {
            s    += g_part[((b*16 + tl)*4 + gt)*2 + 0];
            ssum += g_part[((b*16 + tl)*4 + gt)*2 + 1];
        }
        const float inv = 1.f / 12288.f;
        float mu  = s * inv;
        float var = fmaxf(ssum * inv - mu*mu, 0.f);
        st[gt*2 + 0] = mu;
        st[gt*2 + 1] = rsqrtf(var + EPSV);
    }
    __syncthreads();

    size_t base = (size_t)b * 12 * GG;
    float zi = g_z[base + 0*GG*3 + r];
    float zf = g_z[base + 1*GG*3 + r];
    float zg = g_z[base + 2*GG*3 + r];
    float zo = g_z[base + 3*GG*3 + r];
    zi = (zi - st[0]) * st[1] * lnw[0*12288 + r] + lnb[0*12288 + r];
    zf = (zf - st[2]) * st[3] * lnw[1*12288 + r] + lnb[1*12288 + r];
    zg = (zg - st[4]) * st[5] * lnw[2*12288 + r] + lnb[2*12288 + r];
    zo = (zo - st[6]) * st[7] * lnw[3*12288 + r] + lnb[3*12288 + r];
    float c  = g_c[i];
    float ig = fsig(zi + wci[r]*c);
    float fg = fsig(zf + wcf[r]*c);
    float cn = fg*c + ig*ftanh(zg);
    float og = fsig(zo + wco[r]*cn);
    g_c[i] = cn;
    g_h[i] = og * ftanh(cn);
}

// ---------------- final 37x37 valid conv: h(64,3,64,64) -> out(64,1,28,28) ------
__global__ __launch_bounds__(128) void k_final(const float* __restrict__ cw,
                                               const float* __restrict__ cb,
                                               float* __restrict__ out)
{
    __shared__ float hs[40*64];
    __shared__ float ws[FK*FK];
    const int b   = blockIdx.x / 7;
    const int seg = blockIdx.x % 7;
    const int oy0 = seg * 4;
    const int tid = threadIdx.x;
    const int ly  = tid / 28;      // 0..3 for tid<112
    const int ox  = tid % 28;

    float acc = 0.f;
    for (int hc = 0; hc < HID; hc++) {
        __syncthreads();
        for (int i = tid; i < 40*64; i += 128) {
            int r = i / 64;
            hs[i] = g_h[(size_t)(b*HID + hc)*GG + (oy0 + r)*G + (i - r*64)];
        }
        for (int i = tid; i < FK*FK; i += 128) ws[i] = cw[hc*FK*FK + i];
        __syncthreads();
        if (tid < 112) {
            #pragma unroll 1
            for (int ky = 0; ky < FK; ky++) {
                const float* hr = &hs[(ly + ky)*64 + ox];
                const float* wr = &ws[ky*FK];
                float a = 0.f;
                #pragma unroll
                for (int kx = 0; kx < FK; kx++) a = fmaf(hr[kx], wr[kx], a);
                acc += a;
            }
        }
    }
    if (tid < 112) {
        int oy = oy0 + ly;
        out[b*OUTW*OUTW + oy*OUTW + ox] = acc + cb[0];
    }
}

// ---------------- launch ----------------
extern "C" void kernel_launch(void* const* d_in, const int* in_sizes, int n_in,
                              void* d_out, int out_size)
{
    const float* x   = (const float*)d_in[0];
    const float* Wg  = (const float*)d_in[1];
    const float* bg  = (const float*)d_in[2];
    const float* wci = (const float*)d_in[3];
    const float* wcf = (const float*)d_in[4];
    const float* wco = (const float*)d_in[5];
    const float* lnw = (const float*)d_in[6];
    const float* lnb = (const float*)d_in[7];
    const float* cw  = (const float*)d_in[8];
    const float* cb  = (const float*)d_in[9];
    float* out = (float*)d_out;

    k_init<<<(BB*HID*GG + 255)/256, 256>>>();
    for (int t = 0; t < TT; t++) {
        k_conv<<<BB*16, 128>>>(x, Wg, bg, t);
        k_gates<<<(BB*HID*GG)/256, 256>>>(wci, wcf, wco, lnw, lnb);
    }
    k_final<<<BB*7, 128>>>(cw, cb, out);
}

// round 3
// speedup vs baseline: 1.2934x; 1.0361x over previous
#include <cuda_runtime.h>
#include <math.h>

#define BB   64
#define TT   32
#define HID  3
#define G    64
#define GG   4096
#define NOC  12
#define EPSV 1e-5f
#define FK   37
#define OUTW 28

typedef unsigned long long u64;

// ---------------- packed f32x2 helpers (Blackwell FFMA2 path) ----------------
__device__ __forceinline__ u64 pack2(float x) {
    u64 d; unsigned u = __float_as_uint(x);
    asm("mov.b64 %0, {%1, %1};" : "=l"(d) : "r"(u));
    return d;
}
__device__ __forceinline__ u64 packlh(float lo, float hi) {
    u64 d; unsigned a = __float_as_uint(lo), b = __float_as_uint(hi);
    asm("mov.b64 %0, {%1, %2};" : "=l"(d) : "r"(a), "r"(b));
    return d;
}
__device__ __forceinline__ void ffma2(u64 &acc, u64 a, u64 b) {
    asm("fma.rn.f32x2 %0, %1, %2, %0;" : "+l"(acc) : "l"(a), "l"(b));
}
__device__ __forceinline__ void unpack2(u64 d, float &lo, float &hi) {
    unsigned a, b;
    asm("mov.b64 {%0, %1}, %2;" : "=r"(a), "=r"(b) : "l"(d));
    lo = __uint_as_float(a); hi = __uint_as_float(b);
}

// fast sigmoid / tanh (~1e-6 rel err)
__device__ __forceinline__ float fsig(float x) {
    float t, r;
    asm("mul.f32 %0, %1, 0fBFB8AA3B;" : "=f"(t) : "f"(x));
    asm("ex2.approx.f32 %0, %0;" : "+f"(t));
    asm("add.f32 %0, %0, 0f3F800000;" : "+f"(t));
    asm("rcp.approx.f32 %0, %1;" : "=f"(r) : "f"(t));
    return r;
}
__device__ __forceinline__ float ftanh(float x) {
    return fmaf(2.f, fsig(2.f * x), -1.f);
}

// ---------------- static device scratch ----------------
__device__ float g_h[BB*HID*GG];
__device__ float g_c[BB*HID*GG];
__device__ float g_z[BB*NOC*GG];
__device__ float g_part[BB*8*4*2];

__global__ void k_init() {
    int i = blockIdx.x * blockDim.x + threadIdx.x;
    if (i < BB*HID*GG) { g_h[i] = 0.f; g_c[i] = 0.f; }
}

// ---------------- per-step conv (4ch -> 12ch, 11x11, pad 5) + LN partial sums ---
// grid: BB*8 blocks (16x32 output tile), 128 threads, 4 px / thread
// inner loop: FFMA2 over oc pairs; input pairs hoisted per ky row
__global__ __launch_bounds__(128) void k_conv(const float* __restrict__ x,
                                              const float* __restrict__ Wg,
                                              const float* __restrict__ bg,
                                              int t)
{
    __shared__ __align__(16) float ts[4*26*44];     // input tile, row stride 44
    __shared__ __align__(16) float wsm[4*121*12];   // weights [ic][ky][kx][oc]
    __shared__ float sred[4][8];

    const int tid  = threadIdx.x;
    const int b    = blockIdx.x >> 3;
    const int tile = blockIdx.x & 7;              // 4 row-tiles x 2 col-tiles
    const int ty0  = (tile >> 1) << 4;            // 0,16,32,48
    const int tx0  = (tile & 1) << 5;             // 0,32

    for (int i = tid; i < 4*121*12; i += 128) {
        int oc = i % 12;
        int k  = i / 12;
        int ic = k / 121;
        int kk = k - ic*121;
        wsm[i] = Wg[(oc*4 + ic)*121 + kk];
    }
    const float* xb = x + (size_t)(b*TT + t) * GG;
    for (int i = tid; i < 4*26*42; i += 128) {
        int ic  = i / 1092;
        int rem = i - ic*1092;
        int r   = rem / 42;
        int cc  = rem - r*42;
        int gy = ty0 - 5 + r;
        int gx = tx0 - 5 + cc;
        float v = 0.f;
        if (gy >= 0 && gy < G && gx >= 0 && gx < G) {
            v = (ic == 0) ? xb[gy*G + gx]
                          : g_h[(b*HID + ic - 1)*GG + gy*G + gx];
        }
        ts[(ic*26 + r)*44 + cc] = v;
    }
    __syncthreads();

    const int ty  = tid >> 3;           // 0..15
    const int tx4 = (tid & 7) << 2;     // 0,4,..,28 (local output x base, 4 px)

    // acc[p][j]: pixel p (0..3), oc pair j (2j,2j+1); init with bias
    u64 acc[4][6];
    {
        #pragma unroll
        for (int j = 0; j < 6; j++) {
            u64 bp = packlh(bg[2*j], bg[2*j+1]);
            #pragma unroll
            for (int p = 0; p < 4; p++) acc[p][j] = bp;
        }
    }

    #pragma unroll 1
    for (int ic = 0; ic < 4; ic++) {
        #pragma unroll 1
        for (int ky = 0; ky < 11; ky++) {
            const float* rowp = &ts[(ic*26 + ty + ky)*44 + tx4];
            float win[14];
            #pragma unroll
            for (int w = 0; w < 3; w++) {
                float4 v = ((const float4*)rowp)[w];
                win[4*w]   = v.x; win[4*w+1] = v.y;
                win[4*w+2] = v.z; win[4*w+3] = v.w;
            }
            { float2 v = *(const float2*)(rowp + 12); win[12] = v.x; win[13] = v.y; }
            u64 winp[14];
            #pragma unroll
            for (int j = 0; j < 14; j++) winp[j] = pack2(win[j]);

            const ulonglong2* wp = (const ulonglong2*)&wsm[(ic*121 + ky*11)*12];
            #pragma unroll
            for (int kx = 0; kx < 11; kx++) {
                ulonglong2 p0 = wp[kx*3 + 0];
                ulonglong2 p1 = wp[kx*3 + 1];
                ulonglong2 p2 = wp[kx*3 + 2];
                u64 wv[6];
                wv[0]=p0.x; wv[1]=p0.y; wv[2]=p1.x; wv[3]=p1.y; wv[4]=p2.x; wv[5]=p2.y;
                #pragma unroll
                for (int p = 0; p < 4; p++) {
                    #pragma unroll
                    for (int j = 0; j < 6; j++) ffma2(acc[p][j], winp[kx+p], wv[j]);
                }
            }
        }
    }

    // unpack, store z, LN partial sums
    const int gy = ty0 + ty;
    const int gx = tx0 + tx4;
    float s[4]  = {0.f,0.f,0.f,0.f};
    float ss[4] = {0.f,0.f,0.f,0.f};
    #pragma unroll
    for (int j = 0; j < 6; j++) {
        float z0[4], z1[4];
        #pragma unroll
        for (int p = 0; p < 4; p++) unpack2(acc[p][j], z0[p], z1[p]);
        int gt0 = (2*j)   / 3;
        int gt1 = (2*j+1) / 3;
        float4 v0, v1;
        v0.x=z0[0]; v0.y=z0[1]; v0.z=z0[2]; v0.w=z0[3];
        v1.x=z1[0]; v1.y=z1[1]; v1.z=z1[2]; v1.w=z1[3];
        #pragma unroll
        for (int p = 0; p < 4; p++) {
            s[gt0]  += z0[p];        ss[gt0] += z0[p]*z0[p];
            s[gt1]  += z1[p];        ss[gt1] += z1[p]*z1[p];
        }
        *(float4*)&g_z[(size_t)(b*12 + 2*j  )*GG + gy*G + gx] = v0;
        *(float4*)&g_z[(size_t)(b*12 + 2*j+1)*GG + gy*G + gx] = v1;
    }

    const int lane = tid & 31;
    const int wrp  = tid >> 5;
    #pragma unroll
    for (int g = 0; g < 4; g++) {
        #pragma unroll
        for (int off = 16; off > 0; off >>= 1) {
            s[g]  += __shfl_down_sync(0xFFFFFFFFu, s[g],  off);
            ss[g] += __shfl_down_sync(0xFFFFFFFFu, ss[g], off);
        }
    }
    if (lane == 0) {
        #pragma unroll
        for (int g = 0; g < 4; g++) {
            sred[wrp][g*2 + 0] = s[g];
            sred[wrp][g*2 + 1] = ss[g];
        }
    }
    __syncthreads();
    if (tid < 8) {
        float v = sred[0][tid] + sred[1][tid] + sred[2][tid] + sred[3][tid];
        g_part[((b*8 + tile)*4 + (tid >> 1))*2 + (tid & 1)] = v;
    }
}

// ---------------- pointwise gate update (fused LN-stats finalize) ----------
__global__ __launch_bounds__(256) void k_gates(const float* __restrict__ wci,
                                               const float* __restrict__ wcf,
                                               const float* __restrict__ wco,
                                               const float* __restrict__ lnw,
                                               const float* __restrict__ lnb)
{
    __shared__ float st[8];
    int i = blockIdx.x * 256 + threadIdx.x;
    int b = i / (HID*GG);
    int r = i - b*HID*GG;

    if (threadIdx.x < 4) {
        int gt = threadIdx.x;
        float s = 0.f, ssum = 0.f;
        #pragma unroll
        for (int tl = 0; tl < 8; tl++) {
            s    += g_part[((b*8 + tl)*4 + gt)*2 + 0];
            ssum += g_part[((b*8 + tl)*4 + gt)*2 + 1];
        }
        const float inv = 1.f / 12288.f;
        float mu  = s * inv;
        float var = fmaxf(ssum * inv - mu*mu, 0.f);
        st[gt*2 + 0] = mu;
        st[gt*2 + 1] = rsqrtf(var + EPSV);
    }
    __syncthreads();

    size_t base = (size_t)b * 12 * GG;
    float zi = g_z[base + 0*GG*3 + r];
    float zf = g_z[base + 1*GG*3 + r];
    float zg = g_z[base + 2*GG*3 + r];
    float zo = g_z[base + 3*GG*3 + r];
    zi = (zi - st[0]) * st[1] * lnw[0*12288 + r] + lnb[0*12288 + r];
    zf = (zf - st[2]) * st[3] * lnw[1*12288 + r] + lnb[1*12288 + r];
    zg = (zg - st[4]) * st[5] * lnw[2*12288 + r] + lnb[2*12288 + r];
    zo = (zo - st[6]) * st[7] * lnw[3*12288 + r] + lnb[3*12288 + r];
    float c  = g_c[i];
    float ig = fsig(zi + wci[r]*c);
    float fg = fsig(zf + wcf[r]*c);
    float cn = fg*c + ig*ftanh(zg);
    float og = fsig(zo + wco[r]*cn);
    g_c[i] = cn;
    g_h[i] = og * ftanh(cn);
}

// ---------------- final 37x37 valid conv ----------------
__global__ __launch_bounds__(128) void k_final(const float* __restrict__ cw,
                                               const float* __restrict__ cb,
                                               float* __restrict__ out)
{
    __shared__ float hs[40*64];
    __shared__ float ws[FK*FK];
    const int b   = blockIdx.x / 7;
    const int seg = blockIdx.x % 7;
    const int oy0 = seg * 4;
    const int tid = threadIdx.x;
    const int ly  = tid / 28;
    const int ox  = tid % 28;

    float acc = 0.f;
    for (int hc = 0; hc < HID; hc++) {
        __syncthreads();
        for (int i = tid; i < 40*64; i += 128) {
            int r = i / 64;
            hs[i] = g_h[(size_t)(b*HID + hc)*GG + (oy0 + r)*G + (i - r*64)];
        }
        for (int i = tid; i < FK*FK; i += 128) ws[i] = cw[hc*FK*FK + i];
        __syncthreads();
        if (tid < 112) {
            #pragma unroll 1
            for (int ky = 0; ky < FK; ky++) {
                const float* hr = &hs[(ly + ky)*64 + ox];
                const float* wr = &ws[ky*FK];
                float a = 0.f;
                #pragma unroll
                for (int kx = 0; kx < FK; kx++) a = fmaf(hr[kx], wr[kx], a);
                acc += a;
            }
        }
    }
    if (tid < 112) {
        int oy = oy0 + ly;
        out[b*OUTW*OUTW + oy*OUTW + ox] = acc + cb[0];
    }
}

// ---------------- launch ----------------
extern "C" void kernel_launch(void* const* d_in, const int* in_sizes, int n_in,
                              void* d_out, int out_size)
{
    const float* x   = (const float*)d_in[0];
    const float* Wg  = (const float*)d_in[1];
    const float* bg  = (const float*)d_in[2];
    const float* wci = (const float*)d_in[3];
    const float* wcf = (const float*)d_in[4];
    const float* wco = (const float*)d_in[5];
    const float* lnw = (const float*)d_in[6];
    const float* lnb = (const float*)d_in[7];
    const float* cw  = (const float*)d_in[8];
    const float* cb  = (const float*)d_in[9];
    float* out = (float*)d_out;

    k_init<<<(BB*HID*GG + 255)/256, 256>>>();
    for (int t = 0; t < TT; t++) {
        k_conv<<<BB*8, 128>>>(x, Wg, bg, t);
        k_gates<<<(BB*HID*GG)/256, 256>>>(wci, wcf, wco, lnw, lnb);
    }
    k_final<<<BB*7, 128>>>(cw, cb, out);
}

// round 4
// speedup vs baseline: 1.4114x; 1.0912x over previous
#include <cuda_runtime.h>
#include <math.h>

#define BB   64
#define TT   32
#define HID  3
#define G    64
#define GG   4096
#define NOC  12
#define EPSV 1e-5f
#define FK   37
#define OUTW 28

typedef unsigned long long u64;

// ---------------- packed f32x2 helpers (Blackwell FFMA2 path) ----------------
__device__ __forceinline__ u64 pack2(float x) {
    u64 d; unsigned u = __float_as_uint(x);
    asm("mov.b64 %0, {%1, %1};" : "=l"(d) : "r"(u));
    return d;
}
__device__ __forceinline__ u64 packlh(float lo, float hi) {
    u64 d; unsigned a = __float_as_uint(lo), b = __float_as_uint(hi);
    asm("mov.b64 %0, {%1, %2};" : "=l"(d) : "r"(a), "r"(b));
    return d;
}
__device__ __forceinline__ void ffma2(u64 &acc, u64 a, u64 b) {
    asm("fma.rn.f32x2 %0, %1, %2, %0;" : "+l"(acc) : "l"(a), "l"(b));
}
__device__ __forceinline__ void unpack2(u64 d, float &lo, float &hi) {
    unsigned a, b;
    asm("mov.b64 {%0, %1}, %2;" : "=r"(a), "=r"(b) : "l"(d));
    lo = __uint_as_float(a); hi = __uint_as_float(b);
}

// fast sigmoid / tanh (~1e-6 rel err)
__device__ __forceinline__ float fsig(float x) {
    float t, r;
    asm("mul.f32 %0, %1, 0fBFB8AA3B;" : "=f"(t) : "f"(x));
    asm("ex2.approx.f32 %0, %0;" : "+f"(t));
    asm("add.f32 %0, %0, 0f3F800000;" : "+f"(t));
    asm("rcp.approx.f32 %0, %1;" : "=f"(r) : "f"(t));
    return r;
}
__device__ __forceinline__ float ftanh(float x) {
    return fmaf(2.f, fsig(2.f * x), -1.f);
}

// ---------------- static device scratch ----------------
__device__ float g_h[BB*HID*GG];
__device__ float g_c[BB*HID*GG];
__device__ float g_z[BB*NOC*GG];
__device__ float g_part[BB*8*2*4];   // [b][tile][half][gate_local*2+which]

__global__ void k_init() {
    int i = blockIdx.x * blockDim.x + threadIdx.x;
    if (i < BB*HID*GG) { g_h[i] = 0.f; g_c[i] = 0.f; }
}

// ---------------- per-step conv, split into oc-halves for occupancy -------------
// grid: BB*16 blocks = (b, tile 0..7, half 0..1); 16x32 output tile, 128 thr, 4 px
// half 0 computes oc 0..5 (gates i,f), half 1 computes oc 6..11 (gates g,o)
__global__ __launch_bounds__(128, 7) void k_conv(const float* __restrict__ x,
                                                 const float* __restrict__ Wg,
                                                 const float* __restrict__ bg,
                                                 int t)
{
    __shared__ __align__(16) float ts[4*26*44];     // input tile, row stride 44 (18.3KB)
    __shared__ __align__(16) float wsm[4*121*6];    // weights [ic][ky][kx][oc_local] (11.6KB)
    __shared__ float sred[4][4];

    const int tid  = threadIdx.x;
    const int b    = blockIdx.x >> 4;
    const int rem  = blockIdx.x & 15;
    const int tile = rem >> 1;                    // 0..7: 4 row-tiles x 2 col-tiles
    const int half = rem & 1;
    const int ty0  = (tile >> 1) << 4;            // 0,16,32,48
    const int tx0  = (tile & 1) << 5;             // 0,32

    // weights for this half: wsm[(ic*121+kk)*6 + ocl] = Wg[((half*6+ocl)*4+ic)*121+kk]
    for (int i = tid; i < 4*121*6; i += 128) {
        int ocl = i % 6;
        int k   = i / 6;
        int ic  = k / 121;
        int kk  = k - ic*121;
        wsm[i] = Wg[((half*6 + ocl)*4 + ic)*121 + kk];
    }
    const float* xb = x + (size_t)(b*TT + t) * GG;
    for (int i = tid; i < 4*26*42; i += 128) {
        int ic  = i / 1092;
        int rm  = i - ic*1092;
        int r   = rm / 42;
        int cc  = rm - r*42;
        int gy = ty0 - 5 + r;
        int gx = tx0 - 5 + cc;
        float v = 0.f;
        if (gy >= 0 && gy < G && gx >= 0 && gx < G) {
            v = (ic == 0) ? xb[gy*G + gx]
                          : g_h[(b*HID + ic - 1)*GG + gy*G + gx];
        }
        ts[(ic*26 + r)*44 + cc] = v;
    }
    __syncthreads();

    const int ty  = tid >> 3;           // 0..15
    const int tx4 = (tid & 7) << 2;     // 0,4,..,28

    // acc[p][j]: pixel p, oc pair (half*6+2j, half*6+2j+1); init with bias
    u64 acc[4][3];
    #pragma unroll
    for (int j = 0; j < 3; j++) {
        u64 bp = packlh(bg[half*6 + 2*j], bg[half*6 + 2*j + 1]);
        #pragma unroll
        for (int p = 0; p < 4; p++) acc[p][j] = bp;
    }

    #pragma unroll 1
    for (int ic = 0; ic < 4; ic++) {
        #pragma unroll 1
        for (int ky = 0; ky < 11; ky++) {
            const float* rowp = &ts[(ic*26 + ty + ky)*44 + tx4];
            const u64*   wp   = (const u64*)&wsm[(ic*121 + ky*11)*6];

            // --- section 1: kx = 0..5, needs inputs [0..8] ---
            {
                u64 winp[9];
                {
                    float4 a = ((const float4*)rowp)[0];
                    float4 c = ((const float4*)rowp)[1];
                    float  e = rowp[8];
                    winp[0]=pack2(a.x); winp[1]=pack2(a.y); winp[2]=pack2(a.z); winp[3]=pack2(a.w);
                    winp[4]=pack2(c.x); winp[5]=pack2(c.y); winp[6]=pack2(c.z); winp[7]=pack2(c.w);
                    winp[8]=pack2(e);
                }
                #pragma unroll
                for (int kx = 0; kx < 6; kx++) {
                    u64 w0 = wp[kx*3 + 0];
                    u64 w1 = wp[kx*3 + 1];
                    u64 w2 = wp[kx*3 + 2];
                    #pragma unroll
                    for (int p = 0; p < 4; p++) {
                        ffma2(acc[p][0], winp[kx+p], w0);
                        ffma2(acc[p][1], winp[kx+p], w1);
                        ffma2(acc[p][2], winp[kx+p], w2);
                    }
                }
            }
            // --- section 2: kx = 6..10, needs inputs [6..13] ---
            {
                u64 winp[8];
                {
                    float2 a = *(const float2*)(rowp + 6);
                    float4 c = *(const float4*)(rowp + 8);
                    float2 e = *(const float2*)(rowp + 12);
                    winp[0]=pack2(a.x); winp[1]=pack2(a.y);
                    winp[2]=pack2(c.x); winp[3]=pack2(c.y); winp[4]=pack2(c.z); winp[5]=pack2(c.w);
                    winp[6]=pack2(e.x); winp[7]=pack2(e.y);
                }
                #pragma unroll
                for (int kx = 6; kx < 11; kx++) {
                    u64 w0 = wp[kx*3 + 0];
                    u64 w1 = wp[kx*3 + 1];
                    u64 w2 = wp[kx*3 + 2];
                    #pragma unroll
                    for (int p = 0; p < 4; p++) {
                        ffma2(acc[p][0], winp[kx-6+p], w0);
                        ffma2(acc[p][1], winp[kx-6+p], w1);
                        ffma2(acc[p][2], winp[kx-6+p], w2);
                    }
                }
            }
        }
    }

    // unpack, store z, LN partial sums (this half covers 2 gates)
    const int gy = ty0 + ty;
    const int gx = tx0 + tx4;
    float s[2]  = {0.f, 0.f};
    float ss[2] = {0.f, 0.f};
    #pragma unroll
    for (int j = 0; j < 3; j++) {
        float z0[4], z1[4];
        #pragma unroll
        for (int p = 0; p < 4; p++) unpack2(acc[p][j], z0[p], z1[p]);
        int gl0 = (2*j)   / 3;   // local gate of oc half*6+2j
        int gl1 = (2*j+1) / 3;
        float4 v0, v1;
        v0.x=z0[0]; v0.y=z0[1]; v0.z=z0[2]; v0.w=z0[3];
        v1.x=z1[0]; v1.y=z1[1]; v1.z=z1[2]; v1.w=z1[3];
        #pragma unroll
        for (int p = 0; p < 4; p++) {
            s[gl0]  += z0[p];  ss[gl0] += z0[p]*z0[p];
            s[gl1]  += z1[p];  ss[gl1] += z1[p]*z1[p];
        }
        *(float4*)&g_z[(size_t)(b*12 + half*6 + 2*j    )*GG + gy*G + gx] = v0;
        *(float4*)&g_z[(size_t)(b*12 + half*6 + 2*j + 1)*GG + gy*G + gx] = v1;
    }

    const int lane = tid & 31;
    const int wrp  = tid >> 5;
    #pragma unroll
    for (int g = 0; g < 2; g++) {
        #pragma unroll
        for (int off = 16; off > 0; off >>= 1) {
            s[g]  += __shfl_down_sync(0xFFFFFFFFu, s[g],  off);
            ss[g] += __shfl_down_sync(0xFFFFFFFFu, ss[g], off);
        }
    }
    if (lane == 0) {
        sred[wrp][0] = s[0];  sred[wrp][1] = ss[0];
        sred[wrp][2] = s[1];  sred[wrp][3] = ss[1];
    }
    __syncthreads();
    if (tid < 4) {
        float v = sred[0][tid] + sred[1][tid] + sred[2][tid] + sred[3][tid];
        g_part[((b*8 + tile)*2 + half)*4 + tid] = v;
    }
}

// ---------------- pointwise gate update, float4-vectorized ----------------------
// grid: BB*12 blocks; block covers 1024 consecutive r of one batch b
__global__ __launch_bounds__(256) void k_gates(const float* __restrict__ wci,
                                               const float* __restrict__ wcf,
                                               const float* __restrict__ wco,
                                               const float* __restrict__ lnw,
                                               const float* __restrict__ lnb)
{
    __shared__ float st[8];
    const int b   = blockIdx.x / 12;
    const int r   = ((blockIdx.x % 12) * 256 + threadIdx.x) * 4;   // 0..12284, mult of 4

    if (threadIdx.x < 4) {
        int gt   = threadIdx.x;
        int half = gt >> 1;
        int gl   = gt & 1;
        float s = 0.f, ssum = 0.f;
        #pragma unroll
        for (int tl = 0; tl < 8; tl++) {
            s    += g_part[((b*8 + tl)*2 + half)*4 + gl*2 + 0];
            ssum += g_part[((b*8 + tl)*2 + half)*4 + gl*2 + 1];
        }
        const float inv = 1.f / 12288.f;
        float mu  = s * inv;
        float var = fmaxf(ssum * inv - mu*mu, 0.f);
        st[gt*2 + 0] = mu;
        st[gt*2 + 1] = rsqrtf(var + EPSV);
    }
    __syncthreads();

    const size_t zb = (size_t)b * 12 * GG;
    float4 zi = *(const float4*)&g_z[zb + 0*12288 + r];
    float4 zf = *(const float4*)&g_z[zb + 1*12288 + r];
    float4 zg = *(const float4*)&g_z[zb + 2*12288 + r];
    float4 zo = *(const float4*)&g_z[zb + 3*12288 + r];
    float4 wi = *(const float4*)&lnw[0*12288 + r];
    float4 bi = *(const float4*)&lnb[0*12288 + r];
    float4 wf = *(const float4*)&lnw[1*12288 + r];
    float4 bf = *(const float4*)&lnb[1*12288 + r];
    float4 wg = *(const float4*)&lnw[2*12288 + r];
    float4 bgv= *(const float4*)&lnb[2*12288 + r];
    float4 wo = *(const float4*)&lnw[3*12288 + r];
    float4 bo = *(const float4*)&lnb[3*12288 + r];
    float4 ci = *(const float4*)&wci[r];
    float4 cf = *(const float4*)&wcf[r];
    float4 co = *(const float4*)&wco[r];
    float4 c4 = *(const float4*)&g_c[b*12288 + r];

    float4 cn4, hn4;
    #pragma unroll
    for (int k = 0; k < 4; k++) {
        float vzi = ((const float*)&zi)[k], vzf = ((const float*)&zf)[k];
        float vzg = ((const float*)&zg)[k], vzo = ((const float*)&zo)[k];
        vzi = (vzi - st[0]) * st[1] * ((const float*)&wi)[k] + ((const float*)&bi)[k];
        vzf = (vzf - st[2]) * st[3] * ((const float*)&wf)[k] + ((const float*)&bf)[k];
        vzg = (vzg - st[4]) * st[5] * ((const float*)&wg)[k] + ((const float*)&bgv)[k];
        vzo = (vzo - st[6]) * st[7] * ((const float*)&wo)[k] + ((const float*)&bo)[k];
        float c  = ((const float*)&c4)[k];
        float ig = fsig(vzi + ((const float*)&ci)[k]*c);
        float fg = fsig(vzf + ((const float*)&cf)[k]*c);
        float cn = fg*c + ig*ftanh(vzg);
        float og = fsig(vzo + ((const float*)&co)[k]*cn);
        ((float*)&cn4)[k] = cn;
        ((float*)&hn4)[k] = og * ftanh(cn);
    }
    *(float4*)&g_c[b*12288 + r] = cn4;
    *(float4*)&g_h[b*12288 + r] = hn4;
}

// ---------------- final 37x37 valid conv ----------------
__global__ __launch_bounds__(128) void k_final(const float* __restrict__ cw,
                                               const float* __restrict__ cb,
                                               float* __restrict__ out)
{
    __shared__ float hs[40*64];
    __shared__ float ws[FK*FK];
    const int b   = blockIdx.x / 7;
    const int seg = blockIdx.x % 7;
    const int oy0 = seg * 4;
    const int tid = threadIdx.x;
    const int ly  = tid / 28;
    const int ox  = tid % 28;

    float acc = 0.f;
    for (int hc = 0; hc < HID; hc++) {
        __syncthreads();
        for (int i = tid; i < 40*64; i += 128) {
            int r = i / 64;
            hs[i] = g_h[(size_t)(b*HID + hc)*GG + (oy0 + r)*G + (i - r*64)];
        }
        for (int i = tid; i < FK*FK; i += 128) ws[i] = cw[hc*FK*FK + i];
        __syncthreads();
        if (tid < 112) {
            #pragma unroll 1
            for (int ky = 0; ky < FK; ky++) {
                const float* hr = &hs[(ly + ky)*64 + ox];
                const float* wr = &ws[ky*FK];
                float a = 0.f;
                #pragma unroll
                for (int kx = 0; kx < FK; kx++) a = fmaf(hr[kx], wr[kx], a);
                acc += a;
            }
        }
    }
    if (tid < 112) {
        int oy = oy0 + ly;
        out[b*OUTW*OUTW + oy*OUTW + ox] = acc + cb[0];
    }
}

// ---------------- launch ----------------
extern "C" void kernel_launch(void* const* d_in, const int* in_sizes, int n_in,
                              void* d_out, int out_size)
{
    const float* x   = (const float*)d_in[0];
    const float* Wg  = (const float*)d_in[1];
    const float* bg  = (const float*)d_in[2];
    const float* wci = (const float*)d_in[3];
    const float* wcf = (const float*)d_in[4];
    const float* wco = (const float*)d_in[5];
    const float* lnw = (const float*)d_in[6];
    const float* lnb = (const float*)d_in[7];
    const float* cw  = (const float*)d_in[8];
    const float* cb  = (const float*)d_in[9];
    float* out = (float*)d_out;

    k_init<<<(BB*HID*GG + 255)/256, 256>>>();
    for (int t = 0; t < TT; t++) {
        k_conv<<<BB*16, 128>>>(x, Wg, bg, t);
        k_gates<<<BB*12, 256>>>(wci, wcf, wco, lnw, lnb);
    }
    k_final<<<BB*7, 128>>>(cw, cb, out);
}